// round 15
// baseline (speedup 1.0000x reference)
#include <cuda_runtime.h>
#include <cuda_bf16.h>
#include <cstdint>

#define BB 2
#define SS 1024
#define DD 1024
#define HH 16
#define HD 64
#define HD2 32
#define NSEQ 4
#define SEQP 256
#define DFF 4096
#define NT (BB*SS)
#define SCALING 0.17677669529663687f
#define LAMBDA_INIT 0.2f
#define EPS_DEF 1.1920928955078125e-07f

// ---------------- scratch (device globals; no allocations allowed) ----------------
__device__ float g_h[NT*DD];
__device__ float g_q[NT*DD];
__device__ float g_k[NT*DD];
__device__ float g_v[NT*DD];
__device__ float g_qr[BB*2*HH*SS*HD2];
__device__ float g_kr[BB*2*HH*SS*HD2];
__device__ float g_sc[(size_t)BB*2*HH*SS*SS];   // normalized attention planes
__device__ float g_G[BB*HH*SS];                  // colsums of a1 (atomic)
__device__ float g_Wp[BB*HH*SEQP*HD];
__device__ float g_ao[BB*HH*SS*HD];
__device__ float g_aos[NT*DD];
__device__ float g_x2[NT*DD];
__device__ float g_gate[NT*2*DFF];
__device__ float g_gg[NT*DFF];
__device__ float g_lam;

__device__ __forceinline__ float* bufsel(int id) {
    switch (id) {
        case 0: return g_h;
        case 1: return g_q;
        case 2: return g_k;
        case 3: return g_v;
        case 4: return g_aos;
        case 5: return g_x2;
        case 6: return g_gate;
        case 7: return g_gg;
    }
    return nullptr;
}

__device__ __forceinline__ uint32_t smem_u32(const void* p) {
    uint32_t a;
    asm("{ .reg .u64 t; cvta.to.shared.u64 t, %1; cvt.u32.u64 %0, t; }" : "=r"(a) : "l"(p));
    return a;
}
__device__ __forceinline__ uint32_t cvt_tf32(float x) {
    uint32_t r; asm("cvt.rna.tf32.f32 %0, %1;" : "=r"(r) : "f"(x)); return r;
}
__device__ __forceinline__ uint32_t pack_bf2(float a, float b) {
    __nv_bfloat162 t = __floats2bfloat162_rn(a, b);
    return *reinterpret_cast<uint32_t*>(&t);
}
__device__ __forceinline__ void mma_tf32(float* c, const uint32_t* a, const uint32_t* b) {
    asm volatile(
        "mma.sync.aligned.m16n8k8.row.col.f32.tf32.tf32.f32 "
        "{%0,%1,%2,%3}, {%4,%5,%6,%7}, {%8,%9}, {%0,%1,%2,%3};"
        : "+f"(c[0]), "+f"(c[1]), "+f"(c[2]), "+f"(c[3])
        : "r"(a[0]), "r"(a[1]), "r"(a[2]), "r"(a[3]), "r"(b[0]), "r"(b[1]));
}
__device__ __forceinline__ void mma_bf16(float* c, const uint32_t* a, const uint32_t* b) {
    asm volatile(
        "mma.sync.aligned.m16n8k16.row.col.f32.bf16.bf16.f32 "
        "{%0,%1,%2,%3}, {%4,%5,%6,%7}, {%8,%9}, {%0,%1,%2,%3};"
        : "+f"(c[0]), "+f"(c[1]), "+f"(c[2]), "+f"(c[3])
        : "r"(a[0]), "r"(a[1]), "r"(a[2]), "r"(a[3]), "r"(b[0]), "r"(b[1]));
}
__device__ __forceinline__ void ldm_x4(uint32_t* r, uint32_t addr) {
    asm volatile("ldmatrix.sync.aligned.m8n8.x4.shared.b16 {%0,%1,%2,%3}, [%4];"
        : "=r"(r[0]), "=r"(r[1]), "=r"(r[2]), "=r"(r[3]) : "r"(addr));
}

// ================= tensor-core GEMM: C = A(MxK) * W(NxK)^T + bias (+res) =================
#define KC 16
#define RSW 20            // tf32 row stride words -> ldmatrix conflict-free
#define SZT (128*RSW)
#define RSB 12            // bf16 row stride words -> ldmatrix conflict-free
#define SZB (128*RSB)
#define GSMEM0 (8*SZT*4)  // 81920 B
#define GSMEM1 (8*SZB*4)  // 49152 B

template<int AID, int CID, int RID, bool QKV, int PREC>
__global__ void __launch_bounds__(256, 2) gemm_mma(
    const float* __restrict__ W0, const float* __restrict__ b0,
    const float* __restrict__ W1, const float* __restrict__ b1,
    const float* __restrict__ W2, const float* __restrict__ b2,
    const float* __restrict__ Rext, float* __restrict__ Cext,
    int M, int N, int K)
{
    extern __shared__ uint32_t dsm[];
    const int SZ = (PREC == 0) ? SZT : SZB;
    const int RS = (PREC == 0) ? RSW : RSB;
    uint32_t* SA = dsm;
    uint32_t* SB = dsm + 4*SZ;

    const float* A = bufsel(AID);
    const float* Wm = W0;
    const float* bias = b0;
    float* C;
    if (QKV) {
        int z = blockIdx.z;
        Wm   = (z == 0) ? W0 : (z == 1) ? W1 : W2;
        bias = (z == 0) ? b0 : (z == 1) ? b1 : b2;
        C    = (z == 0) ? g_q : (z == 1) ? g_k : g_v;
    } else {
        C = (CID < 0) ? Cext : bufsel(CID);
    }
    const float* R = (RID == -2) ? nullptr : ((RID == -1) ? Rext : bufsel(RID));

    int tid = threadIdx.x;
    int wid = tid >> 5, lane = tid & 31;
    int m0 = blockIdx.y * 128, n0 = blockIdx.x * 128;
    int wm = (wid & 3) * 32, wn = (wid >> 2) * 64;
    int g = lane >> 2, cc = lane & 3;

    uint32_t a_base, b_base;
    {
        uint32_t sbase = smem_u32(dsm);
        int la_row = wm + (lane & 15);
        int la_col = (lane >> 4) * 4;
        a_base = sbase + (uint32_t)(la_row*RS + la_col) * 4;
        int lb_row = wn + ((lane & 16) >> 1) + (lane & 7);
        int lb_col = ((lane >> 3) & 1) * 4;
        b_base = sbase + (uint32_t)(4*SZ)*4 + (uint32_t)(lb_row*RS + lb_col) * 4;
    }

    float acc[2][8][4];
    #pragma unroll
    for (int mt = 0; mt < 2; mt++)
        #pragma unroll
        for (int nt = 0; nt < 8; nt++)
            #pragma unroll
            for (int r = 0; r < 4; r++) acc[mt][nt][r] = 0.f;

    int lrow = tid >> 1;
    int lk   = (tid & 1) * 8;
    const float* ap = A  + (size_t)(m0 + lrow) * K + lk;
    const float* bp = Wm + (size_t)(n0 + lrow) * K + lk;
    int nk = K / KC;

    float4 pa0 = *(const float4*)ap,       pa1 = *(const float4*)(ap + 4);
    float4 pb0 = *(const float4*)bp,       pb1 = *(const float4*)(bp + 4);

    for (int ks = 0; ks < nk; ks++) {
        int stg = ks & 1;
        {
            float xa[8] = {pa0.x, pa0.y, pa0.z, pa0.w, pa1.x, pa1.y, pa1.z, pa1.w};
            float xb[8] = {pb0.x, pb0.y, pb0.z, pb0.w, pb1.x, pb1.y, pb1.z, pb1.w};
            if (PREC == 0) {
                uint32_t ah[8], al[8], bh[8], bl[8];
                #pragma unroll
                for (int j = 0; j < 8; j++) {
                    ah[j] = cvt_tf32(xa[j]);
                    al[j] = cvt_tf32(xa[j] - __uint_as_float(ah[j]));
                    bh[j] = cvt_tf32(xb[j]);
                    bl[j] = cvt_tf32(xb[j] - __uint_as_float(bh[j]));
                }
                uint32_t* da0 = SA + stg*2*SZ + lrow*RSW + lk;
                uint32_t* da1 = da0 + SZ;
                uint32_t* db0 = SB + stg*2*SZ + lrow*RSW + lk;
                uint32_t* db1 = db0 + SZ;
                *(uint4*)da0       = make_uint4(ah[0], ah[1], ah[2], ah[3]);
                *(uint4*)(da0 + 4) = make_uint4(ah[4], ah[5], ah[6], ah[7]);
                *(uint4*)da1       = make_uint4(al[0], al[1], al[2], al[3]);
                *(uint4*)(da1 + 4) = make_uint4(al[4], al[5], al[6], al[7]);
                *(uint4*)db0       = make_uint4(bh[0], bh[1], bh[2], bh[3]);
                *(uint4*)(db0 + 4) = make_uint4(bh[4], bh[5], bh[6], bh[7]);
                *(uint4*)db1       = make_uint4(bl[0], bl[1], bl[2], bl[3]);
                *(uint4*)(db1 + 4) = make_uint4(bl[4], bl[5], bl[6], bl[7]);
            } else {
                int s = tid & 1;
                uint32_t ahw[4], alw[4], bhw[4], blw[4];
                #pragma unroll
                for (int j = 0; j < 4; j++) {
                    float x0 = xa[2*j], x1 = xa[2*j+1];
                    float h0 = __bfloat162float(__float2bfloat16_rn(x0));
                    float h1 = __bfloat162float(__float2bfloat16_rn(x1));
                    ahw[j] = pack_bf2(h0, h1);
                    alw[j] = pack_bf2(x0 - h0, x1 - h1);
                    float y0 = xb[2*j], y1 = xb[2*j+1];
                    float e0 = __bfloat162float(__float2bfloat16_rn(y0));
                    float e1 = __bfloat162float(__float2bfloat16_rn(y1));
                    bhw[j] = pack_bf2(e0, e1);
                    blw[j] = pack_bf2(y0 - e0, y1 - e1);
                }
                uint32_t* da0 = SA + stg*2*SZ + lrow*RSB + 4*s;
                uint32_t* da1 = da0 + SZ;
                uint32_t* db0 = SB + stg*2*SZ + lrow*RSB + 4*s;
                uint32_t* db1 = db0 + SZ;
                *(uint4*)da0 = make_uint4(ahw[0], ahw[1], ahw[2], ahw[3]);
                *(uint4*)da1 = make_uint4(alw[0], alw[1], alw[2], alw[3]);
                *(uint4*)db0 = make_uint4(bhw[0], bhw[1], bhw[2], bhw[3]);
                *(uint4*)db1 = make_uint4(blw[0], blw[1], blw[2], blw[3]);
            }
        }
        __syncthreads();
        if (ks + 1 < nk) {
            const float* apn = ap + (ks + 1) * KC;
            const float* bpn = bp + (ks + 1) * KC;
            pa0 = *(const float4*)apn;       pa1 = *(const float4*)(apn + 4);
            pb0 = *(const float4*)bpn;       pb1 = *(const float4*)(bpn + 4);
        }
        uint32_t stoff = (uint32_t)(stg*2*SZ) * 4;
        if (PREC == 0) {
            #pragma unroll
            for (int ko = 0; ko < KC; ko += 8) {
                uint32_t koff = stoff + (uint32_t)ko * 4;
                uint32_t af[2][2][4];
                #pragma unroll
                for (int sel = 0; sel < 2; sel++)
                    #pragma unroll
                    for (int mt = 0; mt < 2; mt++)
                        ldm_x4(af[sel][mt],
                               a_base + koff + (uint32_t)(sel*SZT + mt*16*RSW)*4);
                uint32_t bf[2][8][2];
                #pragma unroll
                for (int sel = 0; sel < 2; sel++)
                    #pragma unroll
                    for (int p = 0; p < 4; p++) {
                        uint32_t r4[4];
                        ldm_x4(r4, b_base + koff + (uint32_t)(sel*SZT + p*16*RSW)*4);
                        bf[sel][2*p+0][0] = r4[0]; bf[sel][2*p+0][1] = r4[1];
                        bf[sel][2*p+1][0] = r4[2]; bf[sel][2*p+1][1] = r4[3];
                    }
                #pragma unroll
                for (int nt = 0; nt < 8; nt++)
                    #pragma unroll
                    for (int mt = 0; mt < 2; mt++) {
                        mma_tf32(acc[mt][nt], af[0][mt], bf[0][nt]);
                        mma_tf32(acc[mt][nt], af[1][mt], bf[0][nt]);
                        mma_tf32(acc[mt][nt], af[0][mt], bf[1][nt]);
                    }
            }
        } else {
            uint32_t af[2][2][4];
            #pragma unroll
            for (int sel = 0; sel < 2; sel++)
                #pragma unroll
                for (int mt = 0; mt < 2; mt++)
                    ldm_x4(af[sel][mt],
                           a_base + stoff + (uint32_t)(sel*SZB + mt*16*RSB)*4);
            uint32_t bf[2][8][2];
            #pragma unroll
            for (int sel = 0; sel < 2; sel++)
                #pragma unroll
                for (int p = 0; p < 4; p++) {
                    uint32_t r4[4];
                    ldm_x4(r4, b_base + stoff + (uint32_t)(sel*SZB + p*16*RSB)*4);
                    bf[sel][2*p+0][0] = r4[0]; bf[sel][2*p+0][1] = r4[1];
                    bf[sel][2*p+1][0] = r4[2]; bf[sel][2*p+1][1] = r4[3];
                }
            #pragma unroll
            for (int nt = 0; nt < 8; nt++)
                #pragma unroll
                for (int mt = 0; mt < 2; mt++) {
                    mma_bf16(acc[mt][nt], af[0][mt], bf[0][nt]);
                    mma_bf16(acc[mt][nt], af[1][mt], bf[0][nt]);
                    mma_bf16(acc[mt][nt], af[0][mt], bf[1][nt]);
                }
        }
    }

    #pragma unroll
    for (int mt = 0; mt < 2; mt++) {
        int row0 = m0 + wm + mt*16 + g;
        #pragma unroll
        for (int nt = 0; nt < 8; nt++) {
            int col = n0 + wn + nt*8 + 2*cc;
            float2 bv = *(const float2*)(bias + col);
            float v0 = acc[mt][nt][0] + bv.x;
            float v1 = acc[mt][nt][1] + bv.y;
            float v2 = acc[mt][nt][2] + bv.x;
            float v3 = acc[mt][nt][3] + bv.y;
            if (RID != -2) {
                float2 r0 = *(const float2*)(R + (size_t)row0 * N + col);
                float2 r1 = *(const float2*)(R + (size_t)(row0+8) * N + col);
                v0 += r0.x; v1 += r0.y; v2 += r1.x; v3 += r1.y;
            }
            *(float2*)(C + (size_t)row0 * N + col)     = make_float2(v0, v1);
            *(float2*)(C + (size_t)(row0+8) * N + col) = make_float2(v2, v3);
        }
    }
}

// ---------------- lambda scalar ----------------
__global__ void lam_kernel(const float* __restrict__ lq1, const float* __restrict__ lk1,
                           const float* __restrict__ lq2, const float* __restrict__ lk2) {
    int t = threadIdx.x;
    float a = lq1[t] * lk1[t];
    float b = lq2[t] * lk2[t];
    #pragma unroll
    for (int o = 16; o; o >>= 1) {
        a += __shfl_xor_sync(0xffffffffu, a, o);
        b += __shfl_xor_sync(0xffffffffu, b, o);
    }
    if (t == 0) g_lam = expf(a) - expf(b) + LAMBDA_INIT;
}

__global__ void zeroG_kernel() {
    g_G[blockIdx.x * 256 + threadIdx.x] = 0.f;
}

// ---------------- RMSNorm over 1024, out -> g_h ----------------
template<int SID>
__global__ void rmsnorm_kernel(const float* __restrict__ src_ext, const float* __restrict__ w,
                               float eps) {
    const float* src = (SID < 0) ? src_ext : bufsel(SID);
    int row = blockIdx.x;
    int t = threadIdx.x;
    const float* xr = src + row * 1024;
    float v[4];
    float ss = 0.f;
    #pragma unroll
    for (int i = 0; i < 4; i++) { v[i] = xr[t + i*256]; ss += v[i]*v[i]; }
    __shared__ float red[8];
    #pragma unroll
    for (int o = 16; o; o >>= 1) ss += __shfl_xor_sync(0xffffffffu, ss, o);
    if ((t & 31) == 0) red[t >> 5] = ss;
    __syncthreads();
    if (t == 0) {
        float s = 0.f;
        #pragma unroll
        for (int i = 0; i < 8; i++) s += red[i];
        red[0] = s;
    }
    __syncthreads();
    float scale = rsqrtf(red[0] * (1.0f/1024.0f) + eps);
    float* orow = g_h + row * 1024;
    #pragma unroll
    for (int i = 0; i < 4; i++) { int c = t + i*256; orow[c] = v[i] * scale * w[c]; }
}

// ---------------- RoPE + reorder into (b, a, s'=n*256+p, d) ----------------
__global__ void rope_kernel(const float* __restrict__ fc) {
    int e = blockIdx.x * 256 + threadIdx.x;
    int which = blockIdx.y;
    const float* src = which ? g_k : g_q;
    float* dst = which ? g_kr : g_qr;
    int d  = e & 31;
    int sp = (e >> 5) & 1023;
    int a  = (e >> 15) & 31;
    int b  = e >> 20;
    int p = sp & 255, n = sp >> 8;
    int s = p * 4 + n;
    int base = (b * 1024 + s) * 1024 + a * 32;
    float outv;
    if (p == 0) {
        outv = src[base + d];
    } else {
        int j = d >> 1;
        float c  = fc[(p-1)*32 + j*2 + 0];
        float sn = fc[(p-1)*32 + j*2 + 1];
        float x0 = src[base + (d & ~1)];
        float x1 = src[base + (d | 1)];
        outv = (d & 1) ? (x0*sn + x1*c) : (x0*c - x1*sn);
    }
    dst[e] = outv;
}

// ---------------- fused scores + sign-softmax + colsum(a1) ----------------
// K tile row-major [64][36], Q tile [16][36]; dot-product form, float4 LDS.
#define ATTN_SMEM ((16*1024 + 64*36 + 16*36) * 4)
__global__ void __launch_bounds__(256, 2) attn_fused() {
    extern __shared__ float asmem[];
    float* S  = asmem;               // [16][1024]
    float* Kr = asmem + 16*1024;     // [64][36] row-major K tile
    float* Qs = Kr + 64*36;          // [16][36]
    int plane = blockIdx.y;
    int q0 = blockIdx.x * 16;
    int tid = threadIdx.x;
    const float* qp = g_qr + (size_t)plane * 32768;
    const float* kp = g_kr + (size_t)plane * 32768;

    #pragma unroll
    for (int i = 0; i < 2; i++) {
        int idx = tid + i * 256;
        int r = idx >> 5, d = idx & 31;
        Qs[r*36 + d] = qp[(q0 + r)*32 + d];
    }

    int gq = tid >> 6, c = tid & 63;
    for (int kt = 0; kt < 16; kt++) {
        __syncthreads();
        #pragma unroll
        for (int i = 0; i < 2; i++) {
            int idx = tid*2 + i;
            int k = idx >> 3, d4 = (idx & 7) * 4;
            float4 v = *(const float4*)(kp + (kt*64 + k)*32 + d4);
            *(float4*)&Kr[k*36 + d4] = v;
        }
        __syncthreads();
        float a0 = 0.f, a1 = 0.f, a2 = 0.f, a3 = 0.f;
        const float* krow = Kr + c*36;
        #pragma unroll
        for (int d4 = 0; d4 < 32; d4 += 4) {
            float4 kv = *(const float4*)(krow + d4);
            float4 q0v = *(const float4*)(Qs + (gq*4+0)*36 + d4);
            float4 q1v = *(const float4*)(Qs + (gq*4+1)*36 + d4);
            float4 q2v = *(const float4*)(Qs + (gq*4+2)*36 + d4);
            float4 q3v = *(const float4*)(Qs + (gq*4+3)*36 + d4);
            a0 += q0v.x*kv.x + q0v.y*kv.y + q0v.z*kv.z + q0v.w*kv.w;
            a1 += q1v.x*kv.x + q1v.y*kv.y + q1v.z*kv.z + q1v.w*kv.w;
            a2 += q2v.x*kv.x + q2v.y*kv.y + q2v.z*kv.z + q2v.w*kv.w;
            a3 += q3v.x*kv.x + q3v.y*kv.y + q3v.z*kv.z + q3v.w*kv.w;
        }
        int col = kt*64 + c;
        S[(gq*4+0)*1024 + col] = a0 * SCALING;
        S[(gq*4+1)*1024 + col] = a1 * SCALING;
        S[(gq*4+2)*1024 + col] = a2 * SCALING;
        S[(gq*4+3)*1024 + col] = a3 * SCALING;
    }
    __syncthreads();

    int r = tid >> 4, l16 = tid & 15;
    int pq = (q0 & 255) + r;
    float* row = S + r*1024;
    float m = 0.f;
    #pragma unroll 8
    for (int j = 0; j < 64; j++) {
        int k = l16 + 16*j;
        if ((k & 255) <= pq) m = fmaxf(m, fabsf(row[k]));
    }
    #pragma unroll
    for (int o = 8; o; o >>= 1) m = fmaxf(m, __shfl_xor_sync(0xffffffffu, m, o));
    float Z = 0.f;
    #pragma unroll 8
    for (int j = 0; j < 64; j++) {
        int k = l16 + 16*j;
        float s = row[k];
        bool ok = (k & 255) <= pq;
        float e = ok ? expf(fabsf(s) - m) : 0.f;
        Z += e;
        row[k] = (s > 0.f) ? e : ((s < 0.f) ? -e : 0.f);
    }
    #pragma unroll
    for (int o = 8; o; o >>= 1) Z += __shfl_xor_sync(0xffffffffu, Z, o);
    float inv = 1.f / Z;
    float* gout = g_sc + ((size_t)plane << 20) + (size_t)(q0 + r) * 1024;
    #pragma unroll 8
    for (int j = 0; j < 64; j++) {
        int k = l16 + 16*j;
        float val = row[k] * inv;
        row[k] = val;
        gout[k] = val;
    }
    __syncthreads();

    if ((plane & 1) == 0) {
        int bh = plane >> 1;
        int c0 = tid * 4;
        float s0 = 0.f, s1 = 0.f, s2 = 0.f, s3 = 0.f;
        #pragma unroll
        for (int rr = 0; rr < 16; rr++) {
            float4 v = *(const float4*)(S + rr*1024 + c0);
            s0 += v.x; s1 += v.y; s2 += v.z; s3 += v.w;
        }
        atomicAdd(&g_G[bh*1024 + c0 + 0], s0);
        atomicAdd(&g_G[bh*1024 + c0 + 1], s1);
        atomicAdd(&g_G[bh*1024 + c0 + 2], s2);
        atomicAdd(&g_G[bh*1024 + c0 + 3], s3);
    }
}

// ---------------- Wpre[p,d] = cumsum_p sum_n G[n*256+p]/1024 * v[n*256+p, d] ----------------
__global__ void prefix_kernel() {
    int bh = blockIdx.x;
    int b = bh >> 4, hh = bh & 15;
    int d = threadIdx.x;
    float run = 0.f;
    const float* Gp = g_G + bh * 1024;
    for (int p = 0; p < 256; p++) {
        float gv = 0.f;
        #pragma unroll
        for (int n = 0; n < 4; n++) {
            int k = n*256 + p;
            gv += Gp[k] * g_v[(size_t)(b*1024 + k)*1024 + hh*64 + d];
        }
        run += gv * (1.0f/1024.0f);
        g_Wp[(bh*256 + p)*64 + d] = run;
    }
}

// ---------------- ao = (a1 - lam*a2) @ v + lam*Wpre[p_q] ----------------
__global__ void pv_kernel() {
    int bh = blockIdx.y;
    int b = bh >> 4, hh = bh & 15;
    int q0 = blockIdx.x * 64;
    float lam = g_lam;
    const float* p1 = g_sc + ((size_t)(b*32 + 2*hh) << 20);
    const float* p2 = p1 + (1u << 20);
    __shared__ float Cs[32][64];
    __shared__ float Vs[32][64];
    int t = threadIdx.x;
    int qy = t >> 4, dx = t & 15;
    float acc[4][4];
    #pragma unroll
    for (int i = 0; i < 4; i++)
        #pragma unroll
        for (int j = 0; j < 4; j++) acc[i][j] = 0.f;
    for (int kb = 0; kb < 1024; kb += 32) {
        #pragma unroll
        for (int ii = 0; ii < 2; ii++) {
            int idx = t*2 + ii;
            int row = idx >> 3, c4 = (idx & 7)*4;
            float4 a1v = *(const float4*)(p1 + (size_t)(q0 + row)*1024 + kb + c4);
            float4 a2v = *(const float4*)(p2 + (size_t)(q0 + row)*1024 + kb + c4);
            Cs[c4+0][row] = a1v.x - lam*a2v.x;
            Cs[c4+1][row] = a1v.y - lam*a2v.y;
            Cs[c4+2][row] = a1v.z - lam*a2v.z;
            Cs[c4+3][row] = a1v.w - lam*a2v.w;
            int vr = idx >> 4, d4 = (idx & 15)*4;
            float4 vv = *(const float4*)(g_v + (size_t)(b*1024 + kb + vr)*1024 + hh*64 + d4);
            *(float4*)&Vs[vr][d4] = vv;
        }
        __syncthreads();
        #pragma unroll
        for (int kk = 0; kk < 32; kk++) {
            float4 av = *(const float4*)&Cs[kk][qy*4];
            float4 bv = *(const float4*)&Vs[kk][dx*4];
            acc[0][0] += av.x*bv.x; acc[0][1] += av.x*bv.y; acc[0][2] += av.x*bv.z; acc[0][3] += av.x*bv.w;
            acc[1][0] += av.y*bv.x; acc[1][1] += av.y*bv.y; acc[1][2] += av.y*bv.z; acc[1][3] += av.y*bv.w;
            acc[2][0] += av.z*bv.x; acc[2][1] += av.z*bv.y; acc[2][2] += av.z*bv.z; acc[2][3] += av.z*bv.w;
            acc[3][0] += av.w*bv.x; acc[3][1] += av.w*bv.y; acc[3][2] += av.w*bv.z; acc[3][3] += av.w*bv.w;
        }
        __syncthreads();
    }
    #pragma unroll
    for (int i = 0; i < 4; i++) {
        int q = q0 + qy*4 + i;
        #pragma unroll
        for (int j = 0; j < 4; j++) {
            int d = dx*4 + j;
            g_ao[(size_t)(bh*1024 + q)*64 + d] =
                acc[i][j] + lam * g_Wp[(bh*256 + (q & 255))*64 + d];
        }
    }
}

// ---------------- rms over 64 + scrambled reshape to (B,S,1024) ----------------
__global__ void aonorm_kernel(const float* __restrict__ wat) {
    int row = blockIdx.x;
    int d = threadIdx.x;
    float v = g_ao[(size_t)row*64 + d];
    float ss = v * v;
    #pragma unroll
    for (int o = 16; o; o >>= 1) ss += __shfl_xor_sync(0xffffffffu, ss, o);
    __shared__ float red[2];
    if ((d & 31) == 0) red[d >> 5] = ss;
    __syncthreads();
    float tot = red[0] + red[1];
    float val = v * rsqrtf(tot * (1.0f/64.0f) + 1e-5f) * wat[d];
    int bh = row >> 10, q = row & 1023;
    int b = bh >> 4, hh = bh & 15;
    int sp = hh*64 + (q >> 4);
    int cp = ((q & 15) << 6) + d;
    g_aos[(size_t)(b*1024 + sp)*1024 + cp] = val;
}

// ---------------- SwiGLU: gg = u * silu(vg) ----------------
__global__ void swiglu_kernel() {
    int e = blockIdx.x * 256 + threadIdx.x;
    int tkn = e >> 12, j = e & 4095;
    float u  = g_gate[(size_t)tkn*8192 + j];
    float vg = g_gate[(size_t)tkn*8192 + 4096 + j];
    g_gg[e] = u * (vg / (1.f + expf(-vg)));
}

// ---------------- launch ----------------
extern "C" void kernel_launch(void* const* d_in, const int* in_sizes, int n_in,
                              void* d_out, int out_size) {
    const float* x     = (const float*)d_in[0];
    const float* fc    = (const float*)d_in[1];
    const float* wn1   = (const float*)d_in[2];
    const float* wn2   = (const float*)d_in[3];
    const float* Wq    = (const float*)d_in[4];
    const float* bq    = (const float*)d_in[5];
    const float* Wk    = (const float*)d_in[6];
    const float* bk    = (const float*)d_in[7];
    const float* Wv    = (const float*)d_in[8];
    const float* bv    = (const float*)d_in[9];
    const float* Wo    = (const float*)d_in[10];
    const float* bo    = (const float*)d_in[11];
    const float* lq1   = (const float*)d_in[12];
    const float* lk1   = (const float*)d_in[13];
    const float* lq2   = (const float*)d_in[14];
    const float* lk2   = (const float*)d_in[15];
    const float* wattn = (const float*)d_in[16];
    const float* Wg    = (const float*)d_in[17];
    const float* bg    = (const float*)d_in[18];
    const float* Wout  = (const float*)d_in[19];
    const float* bout  = (const float*)d_in[20];
    float* out = (float*)d_out;

    static int attr_set = 0;
    if (!attr_set) {
        cudaFuncSetAttribute(gemm_mma<0, 0, -2, true, 0>,  cudaFuncAttributeMaxDynamicSharedMemorySize, GSMEM0);
        cudaFuncSetAttribute(gemm_mma<4, 5, -1, false, 1>, cudaFuncAttributeMaxDynamicSharedMemorySize, GSMEM1);
        cudaFuncSetAttribute(gemm_mma<0, 6, -2, false, 1>, cudaFuncAttributeMaxDynamicSharedMemorySize, GSMEM1);
        cudaFuncSetAttribute(gemm_mma<7, -1, 5, false, 1>, cudaFuncAttributeMaxDynamicSharedMemorySize, GSMEM1);
        cudaFuncSetAttribute(attn_fused, cudaFuncAttributeMaxDynamicSharedMemorySize, ATTN_SMEM);
        attr_set = 1;
    }

    lam_kernel<<<1, 32>>>(lq1, lk1, lq2, lk2);
    zeroG_kernel<<<128, 256>>>();

    rmsnorm_kernel<-1><<<NT, 256>>>(x, wn1, EPS_DEF);

    // fused q,k,v GEMMs (tf32 split, ldmatrix)
    gemm_mma<0, 0, -2, true, 0><<<dim3(8, 16, 3), 256, GSMEM0>>>(
        Wq, bq, Wk, bk, Wv, bv, nullptr, nullptr, NT, 1024, 1024);

    rope_kernel<<<dim3(8192, 2), 256>>>(fc);

    // fused scores + sign-softmax + colsum
    attn_fused<<<dim3(64, 64), 256, ATTN_SMEM>>>();

    prefix_kernel<<<32, 64>>>();

    pv_kernel<<<dim3(16, 32), 256>>>();

    aonorm_kernel<<<32768, 64>>>(wattn);

    // x2 = x + aos @ Wo^T + bo (bf16 split, ldmatrix)
    gemm_mma<4, 5, -1, false, 1><<<dim3(8, 16), 256, GSMEM1>>>(
        Wo, bo, nullptr, nullptr, nullptr, nullptr, x, nullptr, NT, 1024, 1024);

    rmsnorm_kernel<5><<<NT, 256>>>(nullptr, wn2, EPS_DEF);

    // gate = h2 @ Wg^T + bg (bf16 split, ldmatrix)
    gemm_mma<0, 6, -2, false, 1><<<dim3(64, 16), 256, GSMEM1>>>(
        Wg, bg, nullptr, nullptr, nullptr, nullptr, nullptr, nullptr, NT, 8192, 1024);

    swiglu_kernel<<<(NT*DFF)/256, 256>>>();

    // out = x2 + gg @ Wout^T + bout (bf16 split, ldmatrix)
    gemm_mma<7, -1, 5, false, 1><<<dim3(8, 16), 256, GSMEM1>>>(
        Wout, bout, nullptr, nullptr, nullptr, nullptr, nullptr, out, NT, 1024, 4096);
}

// round 16
// speedup vs baseline: 1.0216x; 1.0216x over previous
#include <cuda_runtime.h>
#include <cuda_bf16.h>
#include <cstdint>

#define BB 2
#define SS 1024
#define DD 1024
#define HH 16
#define HD 64
#define HD2 32
#define NSEQ 4
#define SEQP 256
#define DFF 4096
#define NT (BB*SS)
#define SCALING 0.17677669529663687f
#define LAMBDA_INIT 0.2f
#define EPS_DEF 1.1920928955078125e-07f

// ---------------- scratch (device globals; no allocations allowed) ----------------
__device__ float g_h[NT*DD];
__device__ float g_q[NT*DD];
__device__ float g_k[NT*DD];
__device__ float g_v[NT*DD];
__device__ float g_qr[BB*2*HH*SS*HD2];
__device__ float g_kr[BB*2*HH*SS*HD2];
__device__ float g_sc[(size_t)BB*2*HH*SS*SS];   // normalized attention planes
__device__ float g_G[BB*HH*SS];                  // colsums of a1 (atomic)
__device__ float g_Wp[BB*HH*SEQP*HD];
__device__ float g_ao[BB*HH*SS*HD];
__device__ float g_aos[NT*DD];
__device__ float g_x2[NT*DD];
__device__ float g_gate[NT*2*DFF];
__device__ float g_gg[NT*DFF];
__device__ float g_lam;

__device__ __forceinline__ float* bufsel(int id) {
    switch (id) {
        case 0: return g_h;
        case 1: return g_q;
        case 2: return g_k;
        case 3: return g_v;
        case 4: return g_aos;
        case 5: return g_x2;
        case 6: return g_gate;
        case 7: return g_gg;
    }
    return nullptr;
}

__device__ __forceinline__ uint32_t smem_u32(const void* p) {
    uint32_t a;
    asm("{ .reg .u64 t; cvta.to.shared.u64 t, %1; cvt.u32.u64 %0, t; }" : "=r"(a) : "l"(p));
    return a;
}
__device__ __forceinline__ uint32_t cvt_tf32(float x) {
    uint32_t r; asm("cvt.rna.tf32.f32 %0, %1;" : "=r"(r) : "f"(x)); return r;
}
__device__ __forceinline__ uint32_t pack_bf2(float a, float b) {
    __nv_bfloat162 t = __floats2bfloat162_rn(a, b);
    return *reinterpret_cast<uint32_t*>(&t);
}
__device__ __forceinline__ void mma_tf32(float* c, const uint32_t* a, const uint32_t* b) {
    asm volatile(
        "mma.sync.aligned.m16n8k8.row.col.f32.tf32.tf32.f32 "
        "{%0,%1,%2,%3}, {%4,%5,%6,%7}, {%8,%9}, {%0,%1,%2,%3};"
        : "+f"(c[0]), "+f"(c[1]), "+f"(c[2]), "+f"(c[3])
        : "r"(a[0]), "r"(a[1]), "r"(a[2]), "r"(a[3]), "r"(b[0]), "r"(b[1]));
}
__device__ __forceinline__ void mma_bf16(float* c, const uint32_t* a, const uint32_t* b) {
    asm volatile(
        "mma.sync.aligned.m16n8k16.row.col.f32.bf16.bf16.f32 "
        "{%0,%1,%2,%3}, {%4,%5,%6,%7}, {%8,%9}, {%0,%1,%2,%3};"
        : "+f"(c[0]), "+f"(c[1]), "+f"(c[2]), "+f"(c[3])
        : "r"(a[0]), "r"(a[1]), "r"(a[2]), "r"(a[3]), "r"(b[0]), "r"(b[1]));
}
__device__ __forceinline__ void ldm_x4(uint32_t* r, uint32_t addr) {
    asm volatile("ldmatrix.sync.aligned.m8n8.x4.shared.b16 {%0,%1,%2,%3}, [%4];"
        : "=r"(r[0]), "=r"(r[1]), "=r"(r[2]), "=r"(r[3]) : "r"(addr));
}

// ================= tensor-core GEMM: C = A(MxK) * W(NxK)^T + bias (+res) =================
#define KC 16
#define RSW 20            // tf32 row stride words -> ldmatrix conflict-free
#define SZT (128*RSW)
#define RSB 12            // bf16 row stride words -> ldmatrix conflict-free
#define SZB (128*RSB)
#define GSMEM0 (8*SZT*4)  // 81920 B
#define GSMEM1 (8*SZB*4)  // 49152 B

template<int AID, int CID, int RID, bool QKV, int PREC>
__global__ void __launch_bounds__(256, 2) gemm_mma(
    const float* __restrict__ W0, const float* __restrict__ b0,
    const float* __restrict__ W1, const float* __restrict__ b1,
    const float* __restrict__ W2, const float* __restrict__ b2,
    const float* __restrict__ Rext, float* __restrict__ Cext,
    int M, int N, int K)
{
    extern __shared__ uint32_t dsm[];
    const int SZ = (PREC == 0) ? SZT : SZB;
    const int RS = (PREC == 0) ? RSW : RSB;
    uint32_t* SA = dsm;
    uint32_t* SB = dsm + 4*SZ;

    const float* A = bufsel(AID);
    const float* Wm = W0;
    const float* bias = b0;
    float* C;
    if (QKV) {
        int z = blockIdx.z;
        Wm   = (z == 0) ? W0 : (z == 1) ? W1 : W2;
        bias = (z == 0) ? b0 : (z == 1) ? b1 : b2;
        C    = (z == 0) ? g_q : (z == 1) ? g_k : g_v;
    } else {
        C = (CID < 0) ? Cext : bufsel(CID);
    }
    const float* R = (RID == -2) ? nullptr : ((RID == -1) ? Rext : bufsel(RID));

    int tid = threadIdx.x;
    int wid = tid >> 5, lane = tid & 31;
    int m0 = blockIdx.y * 128, n0 = blockIdx.x * 128;
    int wm = (wid & 3) * 32, wn = (wid >> 2) * 64;
    int g = lane >> 2, cc = lane & 3;

    uint32_t a_base, b_base;
    {
        uint32_t sbase = smem_u32(dsm);
        int la_row = wm + (lane & 15);
        int la_col = (lane >> 4) * 4;
        a_base = sbase + (uint32_t)(la_row*RS + la_col) * 4;
        int lb_row = wn + ((lane & 16) >> 1) + (lane & 7);
        int lb_col = ((lane >> 3) & 1) * 4;
        b_base = sbase + (uint32_t)(4*SZ)*4 + (uint32_t)(lb_row*RS + lb_col) * 4;
    }

    float acc[2][8][4];
    #pragma unroll
    for (int mt = 0; mt < 2; mt++)
        #pragma unroll
        for (int nt = 0; nt < 8; nt++)
            #pragma unroll
            for (int r = 0; r < 4; r++) acc[mt][nt][r] = 0.f;

    int lrow = tid >> 1;
    int lk   = (tid & 1) * 8;
    const float* ap = A  + (size_t)(m0 + lrow) * K + lk;
    const float* bp = Wm + (size_t)(n0 + lrow) * K + lk;
    int nk = K / KC;

    float4 pa0 = *(const float4*)ap,       pa1 = *(const float4*)(ap + 4);
    float4 pb0 = *(const float4*)bp,       pb1 = *(const float4*)(bp + 4);

    for (int ks = 0; ks < nk; ks++) {
        int stg = ks & 1;
        {
            float xa[8] = {pa0.x, pa0.y, pa0.z, pa0.w, pa1.x, pa1.y, pa1.z, pa1.w};
            float xb[8] = {pb0.x, pb0.y, pb0.z, pb0.w, pb1.x, pb1.y, pb1.z, pb1.w};
            if (PREC == 0) {
                uint32_t ah[8], al[8], bh[8], bl[8];
                #pragma unroll
                for (int j = 0; j < 8; j++) {
                    ah[j] = cvt_tf32(xa[j]);
                    al[j] = cvt_tf32(xa[j] - __uint_as_float(ah[j]));
                    bh[j] = cvt_tf32(xb[j]);
                    bl[j] = cvt_tf32(xb[j] - __uint_as_float(bh[j]));
                }
                uint32_t* da0 = SA + stg*2*SZ + lrow*RSW + lk;
                uint32_t* da1 = da0 + SZ;
                uint32_t* db0 = SB + stg*2*SZ + lrow*RSW + lk;
                uint32_t* db1 = db0 + SZ;
                *(uint4*)da0       = make_uint4(ah[0], ah[1], ah[2], ah[3]);
                *(uint4*)(da0 + 4) = make_uint4(ah[4], ah[5], ah[6], ah[7]);
                *(uint4*)da1       = make_uint4(al[0], al[1], al[2], al[3]);
                *(uint4*)(da1 + 4) = make_uint4(al[4], al[5], al[6], al[7]);
                *(uint4*)db0       = make_uint4(bh[0], bh[1], bh[2], bh[3]);
                *(uint4*)(db0 + 4) = make_uint4(bh[4], bh[5], bh[6], bh[7]);
                *(uint4*)db1       = make_uint4(bl[0], bl[1], bl[2], bl[3]);
                *(uint4*)(db1 + 4) = make_uint4(bl[4], bl[5], bl[6], bl[7]);
            } else {
                int s = tid & 1;
                uint32_t ahw[4], alw[4], bhw[4], blw[4];
                #pragma unroll
                for (int j = 0; j < 4; j++) {
                    float x0 = xa[2*j], x1 = xa[2*j+1];
                    float h0 = __bfloat162float(__float2bfloat16_rn(x0));
                    float h1 = __bfloat162float(__float2bfloat16_rn(x1));
                    ahw[j] = pack_bf2(h0, h1);
                    alw[j] = pack_bf2(x0 - h0, x1 - h1);
                    float y0 = xb[2*j], y1 = xb[2*j+1];
                    float e0 = __bfloat162float(__float2bfloat16_rn(y0));
                    float e1 = __bfloat162float(__float2bfloat16_rn(y1));
                    bhw[j] = pack_bf2(e0, e1);
                    blw[j] = pack_bf2(y0 - e0, y1 - e1);
                }
                uint32_t* da0 = SA + stg*2*SZ + lrow*RSB + 4*s;
                uint32_t* da1 = da0 + SZ;
                uint32_t* db0 = SB + stg*2*SZ + lrow*RSB + 4*s;
                uint32_t* db1 = db0 + SZ;
                *(uint4*)da0 = make_uint4(ahw[0], ahw[1], ahw[2], ahw[3]);
                *(uint4*)da1 = make_uint4(alw[0], alw[1], alw[2], alw[3]);
                *(uint4*)db0 = make_uint4(bhw[0], bhw[1], bhw[2], bhw[3]);
                *(uint4*)db1 = make_uint4(blw[0], blw[1], blw[2], blw[3]);
            }
        }
        __syncthreads();
        if (ks + 1 < nk) {
            const float* apn = ap + (ks + 1) * KC;
            const float* bpn = bp + (ks + 1) * KC;
            pa0 = *(const float4*)apn;       pa1 = *(const float4*)(apn + 4);
            pb0 = *(const float4*)bpn;       pb1 = *(const float4*)(bpn + 4);
        }
        uint32_t stoff = (uint32_t)(stg*2*SZ) * 4;
        if (PREC == 0) {
            #pragma unroll
            for (int ko = 0; ko < KC; ko += 8) {
                uint32_t koff = stoff + (uint32_t)ko * 4;
                uint32_t af[2][2][4];
                #pragma unroll
                for (int sel = 0; sel < 2; sel++)
                    #pragma unroll
                    for (int mt = 0; mt < 2; mt++)
                        ldm_x4(af[sel][mt],
                               a_base + koff + (uint32_t)(sel*SZT + mt*16*RSW)*4);
                uint32_t bf[2][8][2];
                #pragma unroll
                for (int sel = 0; sel < 2; sel++)
                    #pragma unroll
                    for (int p = 0; p < 4; p++) {
                        uint32_t r4[4];
                        ldm_x4(r4, b_base + koff + (uint32_t)(sel*SZT + p*16*RSW)*4);
                        bf[sel][2*p+0][0] = r4[0]; bf[sel][2*p+0][1] = r4[1];
                        bf[sel][2*p+1][0] = r4[2]; bf[sel][2*p+1][1] = r4[3];
                    }
                #pragma unroll
                for (int nt = 0; nt < 8; nt++)
                    #pragma unroll
                    for (int mt = 0; mt < 2; mt++) {
                        mma_tf32(acc[mt][nt], af[0][mt], bf[0][nt]);
                        mma_tf32(acc[mt][nt], af[1][mt], bf[0][nt]);
                        mma_tf32(acc[mt][nt], af[0][mt], bf[1][nt]);
                    }
            }
        } else {
            uint32_t af[2][2][4];
            #pragma unroll
            for (int sel = 0; sel < 2; sel++)
                #pragma unroll
                for (int mt = 0; mt < 2; mt++)
                    ldm_x4(af[sel][mt],
                           a_base + stoff + (uint32_t)(sel*SZB + mt*16*RSB)*4);
            uint32_t bf[2][8][2];
            #pragma unroll
            for (int sel = 0; sel < 2; sel++)
                #pragma unroll
                for (int p = 0; p < 4; p++) {
                    uint32_t r4[4];
                    ldm_x4(r4, b_base + stoff + (uint32_t)(sel*SZB + p*16*RSB)*4);
                    bf[sel][2*p+0][0] = r4[0]; bf[sel][2*p+0][1] = r4[1];
                    bf[sel][2*p+1][0] = r4[2]; bf[sel][2*p+1][1] = r4[3];
                }
            #pragma unroll
            for (int nt = 0; nt < 8; nt++)
                #pragma unroll
                for (int mt = 0; mt < 2; mt++) {
                    mma_bf16(acc[mt][nt], af[0][mt], bf[0][nt]);
                    mma_bf16(acc[mt][nt], af[1][mt], bf[0][nt]);
                    mma_bf16(acc[mt][nt], af[0][mt], bf[1][nt]);
                }
        }
    }

    #pragma unroll
    for (int mt = 0; mt < 2; mt++) {
        int row0 = m0 + wm + mt*16 + g;
        #pragma unroll
        for (int nt = 0; nt < 8; nt++) {
            int col = n0 + wn + nt*8 + 2*cc;
            float2 bv = *(const float2*)(bias + col);
            float v0 = acc[mt][nt][0] + bv.x;
            float v1 = acc[mt][nt][1] + bv.y;
            float v2 = acc[mt][nt][2] + bv.x;
            float v3 = acc[mt][nt][3] + bv.y;
            if (RID != -2) {
                float2 r0 = *(const float2*)(R + (size_t)row0 * N + col);
                float2 r1 = *(const float2*)(R + (size_t)(row0+8) * N + col);
                v0 += r0.x; v1 += r0.y; v2 += r1.x; v3 += r1.y;
            }
            *(float2*)(C + (size_t)row0 * N + col)     = make_float2(v0, v1);
            *(float2*)(C + (size_t)(row0+8) * N + col) = make_float2(v2, v3);
        }
    }
}

// ---------------- lambda scalar ----------------
__global__ void lam_kernel(const float* __restrict__ lq1, const float* __restrict__ lk1,
                           const float* __restrict__ lq2, const float* __restrict__ lk2) {
    int t = threadIdx.x;
    float a = lq1[t] * lk1[t];
    float b = lq2[t] * lk2[t];
    #pragma unroll
    for (int o = 16; o; o >>= 1) {
        a += __shfl_xor_sync(0xffffffffu, a, o);
        b += __shfl_xor_sync(0xffffffffu, b, o);
    }
    if (t == 0) g_lam = expf(a) - expf(b) + LAMBDA_INIT;
}

__global__ void zeroG_kernel() {
    g_G[blockIdx.x * 256 + threadIdx.x] = 0.f;
}

// ---------------- RMSNorm over 1024, out -> g_h ----------------
template<int SID>
__global__ void rmsnorm_kernel(const float* __restrict__ src_ext, const float* __restrict__ w,
                               float eps) {
    const float* src = (SID < 0) ? src_ext : bufsel(SID);
    int row = blockIdx.x;
    int t = threadIdx.x;
    const float* xr = src + row * 1024;
    float v[4];
    float ss = 0.f;
    #pragma unroll
    for (int i = 0; i < 4; i++) { v[i] = xr[t + i*256]; ss += v[i]*v[i]; }
    __shared__ float red[8];
    #pragma unroll
    for (int o = 16; o; o >>= 1) ss += __shfl_xor_sync(0xffffffffu, ss, o);
    if ((t & 31) == 0) red[t >> 5] = ss;
    __syncthreads();
    if (t == 0) {
        float s = 0.f;
        #pragma unroll
        for (int i = 0; i < 8; i++) s += red[i];
        red[0] = s;
    }
    __syncthreads();
    float scale = rsqrtf(red[0] * (1.0f/1024.0f) + eps);
    float* orow = g_h + row * 1024;
    #pragma unroll
    for (int i = 0; i < 4; i++) { int c = t + i*256; orow[c] = v[i] * scale * w[c]; }
}

// ---------------- RoPE + reorder into (b, a, s'=n*256+p, d) ----------------
__global__ void rope_kernel(const float* __restrict__ fc) {
    int e = blockIdx.x * 256 + threadIdx.x;
    int which = blockIdx.y;
    const float* src = which ? g_k : g_q;
    float* dst = which ? g_kr : g_qr;
    int d  = e & 31;
    int sp = (e >> 5) & 1023;
    int a  = (e >> 15) & 31;
    int b  = e >> 20;
    int p = sp & 255, n = sp >> 8;
    int s = p * 4 + n;
    int base = (b * 1024 + s) * 1024 + a * 32;
    float outv;
    if (p == 0) {
        outv = src[base + d];
    } else {
        int j = d >> 1;
        float c  = fc[(p-1)*32 + j*2 + 0];
        float sn = fc[(p-1)*32 + j*2 + 1];
        float x0 = src[base + (d & ~1)];
        float x1 = src[base + (d | 1)];
        outv = (d & 1) ? (x0*sn + x1*c) : (x0*c - x1*sn);
    }
    dst[e] = outv;
}

// ---------------- fused scores + sign-softmax + colsum(a1) ----------------
#define ATTN_SMEM ((16*1024 + 32*65 + 16*33) * 4)
__global__ void __launch_bounds__(256, 2) attn_fused() {
    extern __shared__ float asmem[];
    float* S  = asmem;               // [16][1024]
    float* Ks = asmem + 16*1024;     // [32][65] transposed K tile
    float* Qs = Ks + 32*65;          // [16][33]
    int plane = blockIdx.y;
    int q0 = blockIdx.x * 16;
    int tid = threadIdx.x;
    const float* qp = g_qr + (size_t)plane * 32768;
    const float* kp = g_kr + (size_t)plane * 32768;

    #pragma unroll
    for (int i = 0; i < 2; i++) {
        int idx = tid + i * 256;
        int r = idx >> 5, d = idx & 31;
        Qs[r*33 + d] = qp[(q0 + r)*32 + d];
    }

    int gq = tid >> 6, c = tid & 63;
    for (int kt = 0; kt < 16; kt++) {
        __syncthreads();
        #pragma unroll
        for (int i = 0; i < 2; i++) {
            int idx = tid*2 + i;
            int k = idx >> 3, d4 = (idx & 7) * 4;
            float4 v = *(const float4*)(kp + (kt*64 + k)*32 + d4);
            Ks[(d4+0)*65 + k] = v.x;
            Ks[(d4+1)*65 + k] = v.y;
            Ks[(d4+2)*65 + k] = v.z;
            Ks[(d4+3)*65 + k] = v.w;
        }
        __syncthreads();
        float a0 = 0.f, a1 = 0.f, a2 = 0.f, a3 = 0.f;
        #pragma unroll
        for (int d = 0; d < 32; d++) {
            float kd = Ks[d*65 + c];
            a0 += Qs[(gq*4+0)*33 + d] * kd;
            a1 += Qs[(gq*4+1)*33 + d] * kd;
            a2 += Qs[(gq*4+2)*33 + d] * kd;
            a3 += Qs[(gq*4+3)*33 + d] * kd;
        }
        int col = kt*64 + c;
        S[(gq*4+0)*1024 + col] = a0 * SCALING;
        S[(gq*4+1)*1024 + col] = a1 * SCALING;
        S[(gq*4+2)*1024 + col] = a2 * SCALING;
        S[(gq*4+3)*1024 + col] = a3 * SCALING;
    }
    __syncthreads();

    int r = tid >> 4, l16 = tid & 15;
    int pq = (q0 & 255) + r;
    float* row = S + r*1024;
    float m = 0.f;
    #pragma unroll 8
    for (int j = 0; j < 64; j++) {
        int k = l16 + 16*j;
        if ((k & 255) <= pq) m = fmaxf(m, fabsf(row[k]));
    }
    #pragma unroll
    for (int o = 8; o; o >>= 1) m = fmaxf(m, __shfl_xor_sync(0xffffffffu, m, o));
    float Z = 0.f;
    #pragma unroll 8
    for (int j = 0; j < 64; j++) {
        int k = l16 + 16*j;
        float s = row[k];
        bool ok = (k & 255) <= pq;
        float e = ok ? expf(fabsf(s) - m) : 0.f;
        Z += e;
        row[k] = (s > 0.f) ? e : ((s < 0.f) ? -e : 0.f);
    }
    #pragma unroll
    for (int o = 8; o; o >>= 1) Z += __shfl_xor_sync(0xffffffffu, Z, o);
    float inv = 1.f / Z;
    float* gout = g_sc + ((size_t)plane << 20) + (size_t)(q0 + r) * 1024;
    #pragma unroll 8
    for (int j = 0; j < 64; j++) {
        int k = l16 + 16*j;
        float val = row[k] * inv;
        row[k] = val;
        gout[k] = val;
    }
    __syncthreads();

    if ((plane & 1) == 0) {
        int bh = plane >> 1;
        int c0 = tid * 4;
        float s0 = 0.f, s1 = 0.f, s2 = 0.f, s3 = 0.f;
        #pragma unroll
        for (int rr = 0; rr < 16; rr++) {
            float4 v = *(const float4*)(S + rr*1024 + c0);
            s0 += v.x; s1 += v.y; s2 += v.z; s3 += v.w;
        }
        atomicAdd(&g_G[bh*1024 + c0 + 0], s0);
        atomicAdd(&g_G[bh*1024 + c0 + 1], s1);
        atomicAdd(&g_G[bh*1024 + c0 + 2], s2);
        atomicAdd(&g_G[bh*1024 + c0 + 3], s3);
    }
}

// ---------------- Wpre[p,d] = cumsum_p sum_n G[n*256+p]/1024 * v[n*256+p, d] ----------------
__global__ void prefix_kernel() {
    int bh = blockIdx.x;
    int b = bh >> 4, hh = bh & 15;
    int d = threadIdx.x;
    float run = 0.f;
    const float* Gp = g_G + bh * 1024;
    for (int p = 0; p < 256; p++) {
        float gv = 0.f;
        #pragma unroll
        for (int n = 0; n < 4; n++) {
            int k = n*256 + p;
            gv += Gp[k] * g_v[(size_t)(b*1024 + k)*1024 + hh*64 + d];
        }
        run += gv * (1.0f/1024.0f);
        g_Wp[(bh*256 + p)*64 + d] = run;
    }
}

// ---------------- ao = (a1 - lam*a2) @ v + lam*Wpre[p_q] ----------------
__global__ void pv_kernel() {
    int bh = blockIdx.y;
    int b = bh >> 4, hh = bh & 15;
    int q0 = blockIdx.x * 64;
    float lam = g_lam;
    const float* p1 = g_sc + ((size_t)(b*32 + 2*hh) << 20);
    const float* p2 = p1 + (1u << 20);
    __shared__ float Cs[32][64];
    __shared__ float Vs[32][64];
    int t = threadIdx.x;
    int qy = t >> 4, dx = t & 15;
    float acc[4][4];
    #pragma unroll
    for (int i = 0; i < 4; i++)
        #pragma unroll
        for (int j = 0; j < 4; j++) acc[i][j] = 0.f;
    for (int kb = 0; kb < 1024; kb += 32) {
        #pragma unroll
        for (int ii = 0; ii < 2; ii++) {
            int idx = t*2 + ii;
            int row = idx >> 3, c4 = (idx & 7)*4;
            float4 a1v = *(const float4*)(p1 + (size_t)(q0 + row)*1024 + kb + c4);
            float4 a2v = *(const float4*)(p2 + (size_t)(q0 + row)*1024 + kb + c4);
            Cs[c4+0][row] = a1v.x - lam*a2v.x;
            Cs[c4+1][row] = a1v.y - lam*a2v.y;
            Cs[c4+2][row] = a1v.z - lam*a2v.z;
            Cs[c4+3][row] = a1v.w - lam*a2v.w;
            int vr = idx >> 4, d4 = (idx & 15)*4;
            float4 vv = *(const float4*)(g_v + (size_t)(b*1024 + kb + vr)*1024 + hh*64 + d4);
            *(float4*)&Vs[vr][d4] = vv;
        }
        __syncthreads();
        #pragma unroll
        for (int kk = 0; kk < 32; kk++) {
            float a_[4], b_[4];
            #pragma unroll
            for (int i = 0; i < 4; i++) a_[i] = Cs[kk][qy*4 + i];
            #pragma unroll
            for (int j = 0; j < 4; j++) b_[j] = Vs[kk][dx*4 + j];
            #pragma unroll
            for (int i = 0; i < 4; i++)
                #pragma unroll
                for (int j = 0; j < 4; j++) acc[i][j] += a_[i] * b_[j];
        }
        __syncthreads();
    }
    #pragma unroll
    for (int i = 0; i < 4; i++) {
        int q = q0 + qy*4 + i;
        #pragma unroll
        for (int j = 0; j < 4; j++) {
            int d = dx*4 + j;
            g_ao[(size_t)(bh*1024 + q)*64 + d] =
                acc[i][j] + lam * g_Wp[(bh*256 + (q & 255))*64 + d];
        }
    }
}

// ---------------- rms over 64 + scrambled reshape to (B,S,1024) ----------------
__global__ void aonorm_kernel(const float* __restrict__ wat) {
    int row = blockIdx.x;
    int d = threadIdx.x;
    float v = g_ao[(size_t)row*64 + d];
    float ss = v * v;
    #pragma unroll
    for (int o = 16; o; o >>= 1) ss += __shfl_xor_sync(0xffffffffu, ss, o);
    __shared__ float red[2];
    if ((d & 31) == 0) red[d >> 5] = ss;
    __syncthreads();
    float tot = red[0] + red[1];
    float val = v * rsqrtf(tot * (1.0f/64.0f) + 1e-5f) * wat[d];
    int bh = row >> 10, q = row & 1023;
    int b = bh >> 4, hh = bh & 15;
    int sp = hh*64 + (q >> 4);
    int cp = ((q & 15) << 6) + d;
    g_aos[(size_t)(b*1024 + sp)*1024 + cp] = val;
}

// ---------------- SwiGLU: gg = u * silu(vg) ----------------
__global__ void swiglu_kernel() {
    int e = blockIdx.x * 256 + threadIdx.x;
    int tkn = e >> 12, j = e & 4095;
    float u  = g_gate[(size_t)tkn*8192 + j];
    float vg = g_gate[(size_t)tkn*8192 + 4096 + j];
    g_gg[e] = u * (vg / (1.f + expf(-vg)));
}

// ---------------- launch ----------------
extern "C" void kernel_launch(void* const* d_in, const int* in_sizes, int n_in,
                              void* d_out, int out_size) {
    const float* x     = (const float*)d_in[0];
    const float* fc    = (const float*)d_in[1];
    const float* wn1   = (const float*)d_in[2];
    const float* wn2   = (const float*)d_in[3];
    const float* Wq    = (const float*)d_in[4];
    const float* bq    = (const float*)d_in[5];
    const float* Wk    = (const float*)d_in[6];
    const float* bk    = (const float*)d_in[7];
    const float* Wv    = (const float*)d_in[8];
    const float* bv    = (const float*)d_in[9];
    const float* Wo    = (const float*)d_in[10];
    const float* bo    = (const float*)d_in[11];
    const float* lq1   = (const float*)d_in[12];
    const float* lk1   = (const float*)d_in[13];
    const float* lq2   = (const float*)d_in[14];
    const float* lk2   = (const float*)d_in[15];
    const float* wattn = (const float*)d_in[16];
    const float* Wg    = (const float*)d_in[17];
    const float* bg    = (const float*)d_in[18];
    const float* Wout  = (const float*)d_in[19];
    const float* bout  = (const float*)d_in[20];
    float* out = (float*)d_out;

    static int attr_set = 0;
    if (!attr_set) {
        cudaFuncSetAttribute(gemm_mma<0, 0, -2, true, 0>,  cudaFuncAttributeMaxDynamicSharedMemorySize, GSMEM0);
        cudaFuncSetAttribute(gemm_mma<0, 3, -2, false, 1>, cudaFuncAttributeMaxDynamicSharedMemorySize, GSMEM1);
        cudaFuncSetAttribute(gemm_mma<4, 5, -1, false, 1>, cudaFuncAttributeMaxDynamicSharedMemorySize, GSMEM1);
        cudaFuncSetAttribute(gemm_mma<0, 6, -2, false, 1>, cudaFuncAttributeMaxDynamicSharedMemorySize, GSMEM1);
        cudaFuncSetAttribute(gemm_mma<7, -1, 5, false, 1>, cudaFuncAttributeMaxDynamicSharedMemorySize, GSMEM1);
        cudaFuncSetAttribute(attn_fused, cudaFuncAttributeMaxDynamicSharedMemorySize, ATTN_SMEM);
        attr_set = 1;
    }

    lam_kernel<<<1, 32>>>(lq1, lk1, lq2, lk2);
    zeroG_kernel<<<128, 256>>>();

    rmsnorm_kernel<-1><<<NT, 256>>>(x, wn1, EPS_DEF);

    // q,k GEMMs (tf32 split, ldmatrix; sign-sensitive path)
    gemm_mma<0, 0, -2, true, 0><<<dim3(8, 16, 2), 256, GSMEM0>>>(
        Wq, bq, Wk, bk, nullptr, nullptr, nullptr, nullptr, NT, 1024, 1024);

    // v GEMM (bf16 split, ldmatrix; linear path)
    gemm_mma<0, 3, -2, false, 1><<<dim3(8, 16), 256, GSMEM1>>>(
        Wv, bv, nullptr, nullptr, nullptr, nullptr, nullptr, nullptr, NT, 1024, 1024);

    rope_kernel<<<dim3(8192, 2), 256>>>(fc);

    // fused scores + sign-softmax + colsum
    attn_fused<<<dim3(64, 64), 256, ATTN_SMEM>>>();

    prefix_kernel<<<32, 64>>>();

    pv_kernel<<<dim3(16, 32), 256>>>();

    aonorm_kernel<<<32768, 64>>>(wattn);

    // x2 = x + aos @ Wo^T + bo (bf16 split, ldmatrix)
    gemm_mma<4, 5, -1, false, 1><<<dim3(8, 16), 256, GSMEM1>>>(
        Wo, bo, nullptr, nullptr, nullptr, nullptr, x, nullptr, NT, 1024, 1024);

    rmsnorm_kernel<5><<<NT, 256>>>(nullptr, wn2, EPS_DEF);

    // gate = h2 @ Wg^T + bg (bf16 split, ldmatrix)
    gemm_mma<0, 6, -2, false, 1><<<dim3(64, 16), 256, GSMEM1>>>(
        Wg, bg, nullptr, nullptr, nullptr, nullptr, nullptr, nullptr, NT, 8192, 1024);

    swiglu_kernel<<<(NT*DFF)/256, 256>>>();

    // out = x2 + gg @ Wout^T + bout (bf16 split, ldmatrix)
    gemm_mma<7, -1, 5, false, 1><<<dim3(8, 16), 256, GSMEM1>>>(
        Wout, bout, nullptr, nullptr, nullptr, nullptr, nullptr, out, NT, 1024, 4096);
}

// round 17
// speedup vs baseline: 1.0277x; 1.0060x over previous
#include <cuda_runtime.h>
#include <cuda_bf16.h>
#include <cstdint>

#define BB 2
#define SS 1024
#define DD 1024
#define HH 16
#define HD 64
#define HD2 32
#define NSEQ 4
#define SEQP 256
#define DFF 4096
#define NT (BB*SS)
#define SCALING 0.17677669529663687f
#define LAMBDA_INIT 0.2f
#define EPS_DEF 1.1920928955078125e-07f

// ---------------- scratch (device globals; no allocations allowed) ----------------
__device__ float g_h[NT*DD];
__device__ float g_q[NT*DD];
__device__ float g_k[NT*DD];
__device__ float g_v[NT*DD];
__device__ float g_qr[BB*2*HH*SS*HD2];
__device__ float g_kr[BB*2*HH*SS*HD2];
__device__ float g_sc[(size_t)BB*2*HH*SS*SS];   // normalized attention planes
__device__ float g_G[BB*HH*SS];                  // colsums of a1 (atomic)
__device__ float g_Wp[BB*HH*SEQP*HD];
__device__ float g_ao[BB*HH*SS*HD];
__device__ float g_aos[NT*DD];
__device__ float g_x2[NT*DD];
__device__ float g_gate[NT*2*DFF];
__device__ float g_gg[NT*DFF];
__device__ float g_lam;

__device__ __forceinline__ float* bufsel(int id) {
    switch (id) {
        case 0: return g_h;
        case 1: return g_q;
        case 2: return g_k;
        case 3: return g_v;
        case 4: return g_aos;
        case 5: return g_x2;
        case 6: return g_gate;
        case 7: return g_gg;
    }
    return nullptr;
}

__device__ __forceinline__ uint32_t smem_u32(const void* p) {
    uint32_t a;
    asm("{ .reg .u64 t; cvta.to.shared.u64 t, %1; cvt.u32.u64 %0, t; }" : "=r"(a) : "l"(p));
    return a;
}
__device__ __forceinline__ uint32_t cvt_tf32(float x) {
    uint32_t r; asm("cvt.rna.tf32.f32 %0, %1;" : "=r"(r) : "f"(x)); return r;
}
__device__ __forceinline__ uint32_t pack_bf2(float a, float b) {
    __nv_bfloat162 t = __floats2bfloat162_rn(a, b);
    return *reinterpret_cast<uint32_t*>(&t);
}
__device__ __forceinline__ void mma_tf32(float* c, const uint32_t* a, const uint32_t* b) {
    asm volatile(
        "mma.sync.aligned.m16n8k8.row.col.f32.tf32.tf32.f32 "
        "{%0,%1,%2,%3}, {%4,%5,%6,%7}, {%8,%9}, {%0,%1,%2,%3};"
        : "+f"(c[0]), "+f"(c[1]), "+f"(c[2]), "+f"(c[3])
        : "r"(a[0]), "r"(a[1]), "r"(a[2]), "r"(a[3]), "r"(b[0]), "r"(b[1]));
}
__device__ __forceinline__ void mma_bf16(float* c, const uint32_t* a, const uint32_t* b) {
    asm volatile(
        "mma.sync.aligned.m16n8k16.row.col.f32.bf16.bf16.f32 "
        "{%0,%1,%2,%3}, {%4,%5,%6,%7}, {%8,%9}, {%0,%1,%2,%3};"
        : "+f"(c[0]), "+f"(c[1]), "+f"(c[2]), "+f"(c[3])
        : "r"(a[0]), "r"(a[1]), "r"(a[2]), "r"(a[3]), "r"(b[0]), "r"(b[1]));
}
__device__ __forceinline__ void ldm_x4(uint32_t* r, uint32_t addr) {
    asm volatile("ldmatrix.sync.aligned.m8n8.x4.shared.b16 {%0,%1,%2,%3}, [%4];"
        : "=r"(r[0]), "=r"(r[1]), "=r"(r[2]), "=r"(r[3]) : "r"(addr));
}

// FMA-pipe exp (no MUFU): exp(x) = 2^(x*log2e), poly 2^f on [0,1), err ~3e-7
__device__ __forceinline__ float fexp(float x) {
    float t = fmaxf(x * 1.4426950408889634f, -126.0f);
    float fi = floorf(t);
    float f = t - fi;
    float p = 1.8775767e-3f;
    p = p * f + 8.9893397e-3f;
    p = p * f + 5.5826318e-2f;
    p = p * f + 2.4015361e-1f;
    p = p * f + 6.9315308e-1f;
    p = p * f + 1.0f;
    return __int_as_float(((int)fi + 127) << 23) * p;
}

// ================= tensor-core GEMM: C = A(MxK) * W(NxK)^T + bias (+res) =================
#define KC 16
#define RSW 20            // tf32 row stride words -> ldmatrix conflict-free
#define SZT (128*RSW)
#define RSB 12            // bf16 row stride words -> ldmatrix conflict-free
#define SZB (128*RSB)
#define GSMEM0 (8*SZT*4)  // 81920 B
#define GSMEM1 (8*SZB*4)  // 49152 B

template<int AID, int CID, int RID, bool QKV, int PREC>
__global__ void __launch_bounds__(256, 2) gemm_mma(
    const float* __restrict__ W0, const float* __restrict__ b0,
    const float* __restrict__ W1, const float* __restrict__ b1,
    const float* __restrict__ W2, const float* __restrict__ b2,
    const float* __restrict__ Rext, float* __restrict__ Cext,
    int M, int N, int K)
{
    extern __shared__ uint32_t dsm[];
    const int SZ = (PREC == 0) ? SZT : SZB;
    const int RS = (PREC == 0) ? RSW : RSB;
    uint32_t* SA = dsm;
    uint32_t* SB = dsm + 4*SZ;

    const float* A = bufsel(AID);
    const float* Wm = W0;
    const float* bias = b0;
    float* C;
    if (QKV) {
        int z = blockIdx.z;
        Wm   = (z == 0) ? W0 : (z == 1) ? W1 : W2;
        bias = (z == 0) ? b0 : (z == 1) ? b1 : b2;
        C    = (z == 0) ? g_q : (z == 1) ? g_k : g_v;
    } else {
        C = (CID < 0) ? Cext : bufsel(CID);
    }
    const float* R = (RID == -2) ? nullptr : ((RID == -1) ? Rext : bufsel(RID));

    int tid = threadIdx.x;
    int wid = tid >> 5, lane = tid & 31;
    int m0 = blockIdx.y * 128, n0 = blockIdx.x * 128;
    int wm = (wid & 3) * 32, wn = (wid >> 2) * 64;
    int g = lane >> 2, cc = lane & 3;

    uint32_t a_base, b_base;
    {
        uint32_t sbase = smem_u32(dsm);
        int la_row = wm + (lane & 15);
        int la_col = (lane >> 4) * 4;
        a_base = sbase + (uint32_t)(la_row*RS + la_col) * 4;
        int lb_row = wn + ((lane & 16) >> 1) + (lane & 7);
        int lb_col = ((lane >> 3) & 1) * 4;
        b_base = sbase + (uint32_t)(4*SZ)*4 + (uint32_t)(lb_row*RS + lb_col) * 4;
    }

    float acc[2][8][4];
    #pragma unroll
    for (int mt = 0; mt < 2; mt++)
        #pragma unroll
        for (int nt = 0; nt < 8; nt++)
            #pragma unroll
            for (int r = 0; r < 4; r++) acc[mt][nt][r] = 0.f;

    int lrow = tid >> 1;
    int lk   = (tid & 1) * 8;
    const float* ap = A  + (size_t)(m0 + lrow) * K + lk;
    const float* bp = Wm + (size_t)(n0 + lrow) * K + lk;
    int nk = K / KC;

    float4 pa0 = *(const float4*)ap,       pa1 = *(const float4*)(ap + 4);
    float4 pb0 = *(const float4*)bp,       pb1 = *(const float4*)(bp + 4);

    for (int ks = 0; ks < nk; ks++) {
        int stg = ks & 1;
        {
            float xa[8] = {pa0.x, pa0.y, pa0.z, pa0.w, pa1.x, pa1.y, pa1.z, pa1.w};
            float xb[8] = {pb0.x, pb0.y, pb0.z, pb0.w, pb1.x, pb1.y, pb1.z, pb1.w};
            if (PREC == 0) {
                uint32_t ah[8], al[8], bh[8], bl[8];
                #pragma unroll
                for (int j = 0; j < 8; j++) {
                    ah[j] = cvt_tf32(xa[j]);
                    al[j] = cvt_tf32(xa[j] - __uint_as_float(ah[j]));
                    bh[j] = cvt_tf32(xb[j]);
                    bl[j] = cvt_tf32(xb[j] - __uint_as_float(bh[j]));
                }
                uint32_t* da0 = SA + stg*2*SZ + lrow*RSW + lk;
                uint32_t* da1 = da0 + SZ;
                uint32_t* db0 = SB + stg*2*SZ + lrow*RSW + lk;
                uint32_t* db1 = db0 + SZ;
                *(uint4*)da0       = make_uint4(ah[0], ah[1], ah[2], ah[3]);
                *(uint4*)(da0 + 4) = make_uint4(ah[4], ah[5], ah[6], ah[7]);
                *(uint4*)da1       = make_uint4(al[0], al[1], al[2], al[3]);
                *(uint4*)(da1 + 4) = make_uint4(al[4], al[5], al[6], al[7]);
                *(uint4*)db0       = make_uint4(bh[0], bh[1], bh[2], bh[3]);
                *(uint4*)(db0 + 4) = make_uint4(bh[4], bh[5], bh[6], bh[7]);
                *(uint4*)db1       = make_uint4(bl[0], bl[1], bl[2], bl[3]);
                *(uint4*)(db1 + 4) = make_uint4(bl[4], bl[5], bl[6], bl[7]);
            } else {
                int s = tid & 1;
                uint32_t ahw[4], alw[4], bhw[4], blw[4];
                #pragma unroll
                for (int j = 0; j < 4; j++) {
                    float x0 = xa[2*j], x1 = xa[2*j+1];
                    float h0 = __bfloat162float(__float2bfloat16_rn(x0));
                    float h1 = __bfloat162float(__float2bfloat16_rn(x1));
                    ahw[j] = pack_bf2(h0, h1);
                    alw[j] = pack_bf2(x0 - h0, x1 - h1);
                    float y0 = xb[2*j], y1 = xb[2*j+1];
                    float e0 = __bfloat162float(__float2bfloat16_rn(y0));
                    float e1 = __bfloat162float(__float2bfloat16_rn(y1));
                    bhw[j] = pack_bf2(e0, e1);
                    blw[j] = pack_bf2(y0 - e0, y1 - e1);
                }
                uint32_t* da0 = SA + stg*2*SZ + lrow*RSB + 4*s;
                uint32_t* da1 = da0 + SZ;
                uint32_t* db0 = SB + stg*2*SZ + lrow*RSB + 4*s;
                uint32_t* db1 = db0 + SZ;
                *(uint4*)da0 = make_uint4(ahw[0], ahw[1], ahw[2], ahw[3]);
                *(uint4*)da1 = make_uint4(alw[0], alw[1], alw[2], alw[3]);
                *(uint4*)db0 = make_uint4(bhw[0], bhw[1], bhw[2], bhw[3]);
                *(uint4*)db1 = make_uint4(blw[0], blw[1], blw[2], blw[3]);
            }
        }
        __syncthreads();
        if (ks + 1 < nk) {
            const float* apn = ap + (ks + 1) * KC;
            const float* bpn = bp + (ks + 1) * KC;
            pa0 = *(const float4*)apn;       pa1 = *(const float4*)(apn + 4);
            pb0 = *(const float4*)bpn;       pb1 = *(const float4*)(bpn + 4);
        }
        uint32_t stoff = (uint32_t)(stg*2*SZ) * 4;
        if (PREC == 0) {
            #pragma unroll
            for (int ko = 0; ko < KC; ko += 8) {
                uint32_t koff = stoff + (uint32_t)ko * 4;
                uint32_t af[2][2][4];
                #pragma unroll
                for (int sel = 0; sel < 2; sel++)
                    #pragma unroll
                    for (int mt = 0; mt < 2; mt++)
                        ldm_x4(af[sel][mt],
                               a_base + koff + (uint32_t)(sel*SZT + mt*16*RSW)*4);
                uint32_t bf[2][8][2];
                #pragma unroll
                for (int sel = 0; sel < 2; sel++)
                    #pragma unroll
                    for (int p = 0; p < 4; p++) {
                        uint32_t r4[4];
                        ldm_x4(r4, b_base + koff + (uint32_t)(sel*SZT + p*16*RSW)*4);
                        bf[sel][2*p+0][0] = r4[0]; bf[sel][2*p+0][1] = r4[1];
                        bf[sel][2*p+1][0] = r4[2]; bf[sel][2*p+1][1] = r4[3];
                    }
                #pragma unroll
                for (int nt = 0; nt < 8; nt++)
                    #pragma unroll
                    for (int mt = 0; mt < 2; mt++) {
                        mma_tf32(acc[mt][nt], af[0][mt], bf[0][nt]);
                        mma_tf32(acc[mt][nt], af[1][mt], bf[0][nt]);
                        mma_tf32(acc[mt][nt], af[0][mt], bf[1][nt]);
                    }
            }
        } else {
            uint32_t af[2][2][4];
            #pragma unroll
            for (int sel = 0; sel < 2; sel++)
                #pragma unroll
                for (int mt = 0; mt < 2; mt++)
                    ldm_x4(af[sel][mt],
                           a_base + stoff + (uint32_t)(sel*SZB + mt*16*RSB)*4);
            uint32_t bf[2][8][2];
            #pragma unroll
            for (int sel = 0; sel < 2; sel++)
                #pragma unroll
                for (int p = 0; p < 4; p++) {
                    uint32_t r4[4];
                    ldm_x4(r4, b_base + stoff + (uint32_t)(sel*SZB + p*16*RSB)*4);
                    bf[sel][2*p+0][0] = r4[0]; bf[sel][2*p+0][1] = r4[1];
                    bf[sel][2*p+1][0] = r4[2]; bf[sel][2*p+1][1] = r4[3];
                }
            #pragma unroll
            for (int nt = 0; nt < 8; nt++)
                #pragma unroll
                for (int mt = 0; mt < 2; mt++) {
                    mma_bf16(acc[mt][nt], af[0][mt], bf[0][nt]);
                    mma_bf16(acc[mt][nt], af[1][mt], bf[0][nt]);
                    mma_bf16(acc[mt][nt], af[0][mt], bf[1][nt]);
                }
        }
    }

    #pragma unroll
    for (int mt = 0; mt < 2; mt++) {
        int row0 = m0 + wm + mt*16 + g;
        #pragma unroll
        for (int nt = 0; nt < 8; nt++) {
            int col = n0 + wn + nt*8 + 2*cc;
            float2 bv = *(const float2*)(bias + col);
            float v0 = acc[mt][nt][0] + bv.x;
            float v1 = acc[mt][nt][1] + bv.y;
            float v2 = acc[mt][nt][2] + bv.x;
            float v3 = acc[mt][nt][3] + bv.y;
            if (RID != -2) {
                float2 r0 = *(const float2*)(R + (size_t)row0 * N + col);
                float2 r1 = *(const float2*)(R + (size_t)(row0+8) * N + col);
                v0 += r0.x; v1 += r0.y; v2 += r1.x; v3 += r1.y;
            }
            *(float2*)(C + (size_t)row0 * N + col)     = make_float2(v0, v1);
            *(float2*)(C + (size_t)(row0+8) * N + col) = make_float2(v2, v3);
        }
    }
}

// ---------------- lambda scalar ----------------
__global__ void lam_kernel(const float* __restrict__ lq1, const float* __restrict__ lk1,
                           const float* __restrict__ lq2, const float* __restrict__ lk2) {
    int t = threadIdx.x;
    float a = lq1[t] * lk1[t];
    float b = lq2[t] * lk2[t];
    #pragma unroll
    for (int o = 16; o; o >>= 1) {
        a += __shfl_xor_sync(0xffffffffu, a, o);
        b += __shfl_xor_sync(0xffffffffu, b, o);
    }
    if (t == 0) g_lam = expf(a) - expf(b) + LAMBDA_INIT;
}

__global__ void zeroG_kernel() {
    g_G[blockIdx.x * 256 + threadIdx.x] = 0.f;
}

// ---------------- RMSNorm over 1024, out -> g_h ----------------
template<int SID>
__global__ void rmsnorm_kernel(const float* __restrict__ src_ext, const float* __restrict__ w,
                               float eps) {
    const float* src = (SID < 0) ? src_ext : bufsel(SID);
    int row = blockIdx.x;
    int t = threadIdx.x;
    const float* xr = src + row * 1024;
    float v[4];
    float ss = 0.f;
    #pragma unroll
    for (int i = 0; i < 4; i++) { v[i] = xr[t + i*256]; ss += v[i]*v[i]; }
    __shared__ float red[8];
    #pragma unroll
    for (int o = 16; o; o >>= 1) ss += __shfl_xor_sync(0xffffffffu, ss, o);
    if ((t & 31) == 0) red[t >> 5] = ss;
    __syncthreads();
    if (t == 0) {
        float s = 0.f;
        #pragma unroll
        for (int i = 0; i < 8; i++) s += red[i];
        red[0] = s;
    }
    __syncthreads();
    float scale = rsqrtf(red[0] * (1.0f/1024.0f) + eps);
    float* orow = g_h + row * 1024;
    #pragma unroll
    for (int i = 0; i < 4; i++) { int c = t + i*256; orow[c] = v[i] * scale * w[c]; }
}

// ---------------- RoPE + reorder into (b, a, s'=n*256+p, d) ----------------
__global__ void rope_kernel(const float* __restrict__ fc) {
    int e = blockIdx.x * 256 + threadIdx.x;
    int which = blockIdx.y;
    const float* src = which ? g_k : g_q;
    float* dst = which ? g_kr : g_qr;
    int d  = e & 31;
    int sp = (e >> 5) & 1023;
    int a  = (e >> 15) & 31;
    int b  = e >> 20;
    int p = sp & 255, n = sp >> 8;
    int s = p * 4 + n;
    int base = (b * 1024 + s) * 1024 + a * 32;
    float outv;
    if (p == 0) {
        outv = src[base + d];
    } else {
        int j = d >> 1;
        float c  = fc[(p-1)*32 + j*2 + 0];
        float sn = fc[(p-1)*32 + j*2 + 1];
        float x0 = src[base + (d & ~1)];
        float x1 = src[base + (d | 1)];
        outv = (d & 1) ? (x0*sn + x1*c) : (x0*c - x1*sn);
    }
    dst[e] = outv;
}

// ---------------- fused scores + sign-softmax + colsum(a1) ----------------
#define ATTN_SMEM ((16*1024 + 32*65 + 16*33) * 4)
__global__ void __launch_bounds__(256, 2) attn_fused() {
    extern __shared__ float asmem[];
    float* S  = asmem;               // [16][1024]
    float* Ks = asmem + 16*1024;     // [32][65] transposed K tile
    float* Qs = Ks + 32*65;          // [16][33]
    int plane = blockIdx.y;
    int q0 = blockIdx.x * 16;
    int tid = threadIdx.x;
    const float* qp = g_qr + (size_t)plane * 32768;
    const float* kp = g_kr + (size_t)plane * 32768;

    #pragma unroll
    for (int i = 0; i < 2; i++) {
        int idx = tid + i * 256;
        int r = idx >> 5, d = idx & 31;
        Qs[r*33 + d] = qp[(q0 + r)*32 + d];
    }

    int gq = tid >> 6, c = tid & 63;
    for (int kt = 0; kt < 16; kt++) {
        __syncthreads();
        #pragma unroll
        for (int i = 0; i < 2; i++) {
            int idx = tid*2 + i;
            int k = idx >> 3, d4 = (idx & 7) * 4;
            float4 v = *(const float4*)(kp + (kt*64 + k)*32 + d4);
            Ks[(d4+0)*65 + k] = v.x;
            Ks[(d4+1)*65 + k] = v.y;
            Ks[(d4+2)*65 + k] = v.z;
            Ks[(d4+3)*65 + k] = v.w;
        }
        __syncthreads();
        float a0 = 0.f, a1 = 0.f, a2 = 0.f, a3 = 0.f;
        #pragma unroll
        for (int d = 0; d < 32; d++) {
            float kd = Ks[d*65 + c];
            a0 += Qs[(gq*4+0)*33 + d] * kd;
            a1 += Qs[(gq*4+1)*33 + d] * kd;
            a2 += Qs[(gq*4+2)*33 + d] * kd;
            a3 += Qs[(gq*4+3)*33 + d] * kd;
        }
        int col = kt*64 + c;
        S[(gq*4+0)*1024 + col] = a0 * SCALING;
        S[(gq*4+1)*1024 + col] = a1 * SCALING;
        S[(gq*4+2)*1024 + col] = a2 * SCALING;
        S[(gq*4+3)*1024 + col] = a3 * SCALING;
    }
    __syncthreads();

    int r = tid >> 4, l16 = tid & 15;
    int pq = (q0 & 255) + r;
    float* row = S + r*1024;
    float m = 0.f;
    #pragma unroll 8
    for (int j = 0; j < 64; j++) {
        int k = l16 + 16*j;
        if ((k & 255) <= pq) m = fmaxf(m, fabsf(row[k]));
    }
    #pragma unroll
    for (int o = 8; o; o >>= 1) m = fmaxf(m, __shfl_xor_sync(0xffffffffu, m, o));
    float Z = 0.f;
    #pragma unroll 8
    for (int j = 0; j < 64; j++) {
        int k = l16 + 16*j;
        float s = row[k];
        bool ok = (k & 255) <= pq;
        float e = ok ? fexp(fabsf(s) - m) : 0.f;
        Z += e;
        row[k] = (s > 0.f) ? e : ((s < 0.f) ? -e : 0.f);
    }
    #pragma unroll
    for (int o = 8; o; o >>= 1) Z += __shfl_xor_sync(0xffffffffu, Z, o);
    float inv = 1.f / Z;
    float* gout = g_sc + ((size_t)plane << 20) + (size_t)(q0 + r) * 1024;
    #pragma unroll 8
    for (int j = 0; j < 64; j++) {
        int k = l16 + 16*j;
        float val = row[k] * inv;
        row[k] = val;
        gout[k] = val;
    }
    __syncthreads();

    if ((plane & 1) == 0) {
        int bh = plane >> 1;
        int c0 = tid * 4;
        float s0 = 0.f, s1 = 0.f, s2 = 0.f, s3 = 0.f;
        #pragma unroll
        for (int rr = 0; rr < 16; rr++) {
            float4 v = *(const float4*)(S + rr*1024 + c0);
            s0 += v.x; s1 += v.y; s2 += v.z; s3 += v.w;
        }
        atomicAdd(&g_G[bh*1024 + c0 + 0], s0);
        atomicAdd(&g_G[bh*1024 + c0 + 1], s1);
        atomicAdd(&g_G[bh*1024 + c0 + 2], s2);
        atomicAdd(&g_G[bh*1024 + c0 + 3], s3);
    }
}

// ---------------- Wpre[p,d] = cumsum_p sum_n G[n*256+p]/1024 * v[n*256+p, d] ----------------
__global__ void prefix_kernel() {
    int bh = blockIdx.x;
    int b = bh >> 4, hh = bh & 15;
    int d = threadIdx.x;
    float run = 0.f;
    const float* Gp = g_G + bh * 1024;
    for (int p = 0; p < 256; p++) {
        float gv = 0.f;
        #pragma unroll
        for (int n = 0; n < 4; n++) {
            int k = n*256 + p;
            gv += Gp[k] * g_v[(size_t)(b*1024 + k)*1024 + hh*64 + d];
        }
        run += gv * (1.0f/1024.0f);
        g_Wp[(bh*256 + p)*64 + d] = run;
    }
}

// ---------------- ao = (a1 - lam*a2) @ v + lam*Wpre[p_q] ----------------
__global__ void pv_kernel() {
    int bh = blockIdx.y;
    int b = bh >> 4, hh = bh & 15;
    int q0 = blockIdx.x * 64;
    float lam = g_lam;
    const float* p1 = g_sc + ((size_t)(b*32 + 2*hh) << 20);
    const float* p2 = p1 + (1u << 20);
    __shared__ float Cs[32][64];
    __shared__ float Vs[32][64];
    int t = threadIdx.x;
    int qy = t >> 4, dx = t & 15;
    float acc[4][4];
    #pragma unroll
    for (int i = 0; i < 4; i++)
        #pragma unroll
        for (int j = 0; j < 4; j++) acc[i][j] = 0.f;
    for (int kb = 0; kb < 1024; kb += 32) {
        #pragma unroll
        for (int ii = 0; ii < 2; ii++) {
            int idx = t*2 + ii;
            int row = idx >> 3, c4 = (idx & 7)*4;
            float4 a1v = *(const float4*)(p1 + (size_t)(q0 + row)*1024 + kb + c4);
            float4 a2v = *(const float4*)(p2 + (size_t)(q0 + row)*1024 + kb + c4);
            Cs[c4+0][row] = a1v.x - lam*a2v.x;
            Cs[c4+1][row] = a1v.y - lam*a2v.y;
            Cs[c4+2][row] = a1v.z - lam*a2v.z;
            Cs[c4+3][row] = a1v.w - lam*a2v.w;
            int vr = idx >> 4, d4 = (idx & 15)*4;
            float4 vv = *(const float4*)(g_v + (size_t)(b*1024 + kb + vr)*1024 + hh*64 + d4);
            *(float4*)&Vs[vr][d4] = vv;
        }
        __syncthreads();
        #pragma unroll
        for (int kk = 0; kk < 32; kk++) {
            float a_[4], b_[4];
            #pragma unroll
            for (int i = 0; i < 4; i++) a_[i] = Cs[kk][qy*4 + i];
            #pragma unroll
            for (int j = 0; j < 4; j++) b_[j] = Vs[kk][dx*4 + j];
            #pragma unroll
            for (int i = 0; i < 4; i++)
                #pragma unroll
                for (int j = 0; j < 4; j++) acc[i][j] += a_[i] * b_[j];
        }
        __syncthreads();
    }
    #pragma unroll
    for (int i = 0; i < 4; i++) {
        int q = q0 + qy*4 + i;
        #pragma unroll
        for (int j = 0; j < 4; j++) {
            int d = dx*4 + j;
            g_ao[(size_t)(bh*1024 + q)*64 + d] =
                acc[i][j] + lam * g_Wp[(bh*256 + (q & 255))*64 + d];
        }
    }
}

// ---------------- rms over 64 + scrambled reshape to (B,S,1024) ----------------
__global__ void aonorm_kernel(const float* __restrict__ wat) {
    int row = blockIdx.x;
    int d = threadIdx.x;
    float v = g_ao[(size_t)row*64 + d];
    float ss = v * v;
    #pragma unroll
    for (int o = 16; o; o >>= 1) ss += __shfl_xor_sync(0xffffffffu, ss, o);
    __shared__ float red[2];
    if ((d & 31) == 0) red[d >> 5] = ss;
    __syncthreads();
    float tot = red[0] + red[1];
    float val = v * rsqrtf(tot * (1.0f/64.0f) + 1e-5f) * wat[d];
    int bh = row >> 10, q = row & 1023;
    int b = bh >> 4, hh = bh & 15;
    int sp = hh*64 + (q >> 4);
    int cp = ((q & 15) << 6) + d;
    g_aos[(size_t)(b*1024 + sp)*1024 + cp] = val;
}

// ---------------- SwiGLU: gg = u * silu(vg) ----------------
__global__ void swiglu_kernel() {
    int e = blockIdx.x * 256 + threadIdx.x;
    int tkn = e >> 12, j = e & 4095;
    float u  = g_gate[(size_t)tkn*8192 + j];
    float vg = g_gate[(size_t)tkn*8192 + 4096 + j];
    g_gg[e] = u * (vg / (1.f + fexp(-vg)));
}

// ---------------- launch ----------------
extern "C" void kernel_launch(void* const* d_in, const int* in_sizes, int n_in,
                              void* d_out, int out_size) {
    const float* x     = (const float*)d_in[0];
    const float* fc    = (const float*)d_in[1];
    const float* wn1   = (const float*)d_in[2];
    const float* wn2   = (const float*)d_in[3];
    const float* Wq    = (const float*)d_in[4];
    const float* bq    = (const float*)d_in[5];
    const float* Wk    = (const float*)d_in[6];
    const float* bk    = (const float*)d_in[7];
    const float* Wv    = (const float*)d_in[8];
    const float* bv    = (const float*)d_in[9];
    const float* Wo    = (const float*)d_in[10];
    const float* bo    = (const float*)d_in[11];
    const float* lq1   = (const float*)d_in[12];
    const float* lk1   = (const float*)d_in[13];
    const float* lq2   = (const float*)d_in[14];
    const float* lk2   = (const float*)d_in[15];
    const float* wattn = (const float*)d_in[16];
    const float* Wg    = (const float*)d_in[17];
    const float* bg    = (const float*)d_in[18];
    const float* Wout  = (const float*)d_in[19];
    const float* bout  = (const float*)d_in[20];
    float* out = (float*)d_out;

    static int attr_set = 0;
    if (!attr_set) {
        cudaFuncSetAttribute(gemm_mma<0, 0, -2, true, 0>,  cudaFuncAttributeMaxDynamicSharedMemorySize, GSMEM0);
        cudaFuncSetAttribute(gemm_mma<0, 3, -2, false, 1>, cudaFuncAttributeMaxDynamicSharedMemorySize, GSMEM1);
        cudaFuncSetAttribute(gemm_mma<4, 5, -1, false, 1>, cudaFuncAttributeMaxDynamicSharedMemorySize, GSMEM1);
        cudaFuncSetAttribute(gemm_mma<0, 6, -2, false, 1>, cudaFuncAttributeMaxDynamicSharedMemorySize, GSMEM1);
        cudaFuncSetAttribute(gemm_mma<7, -1, 5, false, 1>, cudaFuncAttributeMaxDynamicSharedMemorySize, GSMEM1);
        cudaFuncSetAttribute(attn_fused, cudaFuncAttributeMaxDynamicSharedMemorySize, ATTN_SMEM);
        attr_set = 1;
    }

    lam_kernel<<<1, 32>>>(lq1, lk1, lq2, lk2);
    zeroG_kernel<<<128, 256>>>();

    rmsnorm_kernel<-1><<<NT, 256>>>(x, wn1, EPS_DEF);

    // q,k GEMMs (tf32 split, ldmatrix; sign-sensitive path)
    gemm_mma<0, 0, -2, true, 0><<<dim3(8, 16, 2), 256, GSMEM0>>>(
        Wq, bq, Wk, bk, nullptr, nullptr, nullptr, nullptr, NT, 1024, 1024);

    // v GEMM (bf16 split, ldmatrix; linear path)
    gemm_mma<0, 3, -2, false, 1><<<dim3(8, 16), 256, GSMEM1>>>(
        Wv, bv, nullptr, nullptr, nullptr, nullptr, nullptr, nullptr, NT, 1024, 1024);

    rope_kernel<<<dim3(8192, 2), 256>>>(fc);

    // fused scores + sign-softmax + colsum
    attn_fused<<<dim3(64, 64), 256, ATTN_SMEM>>>();

    prefix_kernel<<<32, 64>>>();

    pv_kernel<<<dim3(16, 32), 256>>>();

    aonorm_kernel<<<32768, 64>>>(wattn);

    // x2 = x + aos @ Wo^T + bo (bf16 split, ldmatrix)
    gemm_mma<4, 5, -1, false, 1><<<dim3(8, 16), 256, GSMEM1>>>(
        Wo, bo, nullptr, nullptr, nullptr, nullptr, x, nullptr, NT, 1024, 1024);

    rmsnorm_kernel<5><<<NT, 256>>>(nullptr, wn2, EPS_DEF);

    // gate = h2 @ Wg^T + bg (bf16 split, ldmatrix)
    gemm_mma<0, 6, -2, false, 1><<<dim3(64, 16), 256, GSMEM1>>>(
        Wg, bg, nullptr, nullptr, nullptr, nullptr, nullptr, nullptr, NT, 8192, 1024);

    swiglu_kernel<<<(NT*DFF)/256, 256>>>();

    // out = x2 + gg @ Wout^T + bout (bf16 split, ldmatrix)
    gemm_mma<7, -1, 5, false, 1><<<dim3(8, 16), 256, GSMEM1>>>(
        Wout, bout, nullptr, nullptr, nullptr, nullptr, nullptr, out, NT, 1024, 4096);
}